// round 10
// baseline (speedup 1.0000x reference)
#include <cuda_runtime.h>
#include <cuda_bf16.h>
#include <cstdint>

// ============================================================
// bf16 3-term split HMMA. h1 built cooperatively ONCE into SMEM (hi/lo),
// k-loop is pure ldmatrix + mma (zero ALU). CTA = 256 thr, 2 samples (M=128).
// Warp = 16 rows x 64 cols. W2 prepacked into device globals.
// ============================================================

#define LDAB 72   // bf16 row stride (144 B)
#define BPK_U4 (64 * LDAB * 2 / 16)   // 576 uint4 per tile

__device__ uint4 g_Bhi4[BPK_U4];
__device__ uint4 g_Blo4[BPK_U4];

__device__ __forceinline__ uint32_t smem_u32(const void* p) {
    uint32_t a;
    asm("{ .reg .u64 t; cvta.to.shared.u64 t, %1; cvt.u32.u64 %0, t; }" : "=r"(a) : "l"(p));
    return a;
}

__device__ __forceinline__ void ldsm4(uint32_t r[4], uint32_t addr) {
    asm volatile("ldmatrix.sync.aligned.m8n8.x4.shared.b16 {%0,%1,%2,%3}, [%4];"
                 : "=r"(r[0]), "=r"(r[1]), "=r"(r[2]), "=r"(r[3]) : "r"(addr));
}

__device__ __forceinline__ void mma16816(float c[4], const uint32_t a[4],
                                          uint32_t b0, uint32_t b1) {
    asm volatile("mma.sync.aligned.m16n8k16.row.col.f32.bf16.bf16.f32 "
                 "{%0,%1,%2,%3}, {%4,%5,%6,%7}, {%8,%9}, {%0,%1,%2,%3};"
                 : "+f"(c[0]), "+f"(c[1]), "+f"(c[2]), "+f"(c[3])
                 : "r"(a[0]), "r"(a[1]), "r"(a[2]), "r"(a[3]), "r"(b0), "r"(b1));
}

__device__ __forceinline__ void split_pack(float a, float b, uint32_t& hi, uint32_t& lo) {
    __nv_bfloat16 ah = __float2bfloat16(a);
    __nv_bfloat16 bh = __float2bfloat16(b);
    __nv_bfloat162 hp; hp.x = ah; hp.y = bh;
    __nv_bfloat162 lp = __floats2bfloat162_rn(a - __bfloat162float(ah),
                                              b - __bfloat162float(bh));
    hi = *reinterpret_cast<uint32_t*>(&hp);
    lo = *reinterpret_cast<uint32_t*>(&lp);
}

// triu(9) index tables
__constant__ unsigned char c_iu_i[45] = {
    0,0,0,0,0,0,0,0,0, 1,1,1,1,1,1,1,1, 2,2,2,2,2,2,2,
    3,3,3,3,3,3, 4,4,4,4,4, 5,5,5,5, 6,6,6, 7,7, 8};
__constant__ unsigned char c_iu_j[45] = {
    0,1,2,3,4,5,6,7,8, 1,2,3,4,5,6,7,8, 2,3,4,5,6,7,8,
    3,4,5,6,7,8, 4,5,6,7,8, 5,6,7,8, 6,7,8, 7,8, 8};

// ---- dynamic SMEM layout (bytes) ----
#define OFF_BHI 0        // 9216
#define OFF_BLO 9216     // 9216
#define OFF_AHI 18432    // 18432 (128 rows x 72 bf16)
#define OFF_ALO 36864    // 18432
#define OFF_F   55296    // float region
#define SMEM_BYTES (55296 + 4120 * 4)   // 71776

// float misc region offsets (floats, relative to OFF_F)
#define F_CTXW 0       // 2835
#define F_W1   2836    // 128 (byte 11344 -> 16B aligned)
#define F_B1   2964    // 64
#define F_B2   3028    // 64
#define F_W3   3092    // 128 (byte 12368, 16B aligned)
#define F_GW   3220    // 49
#define F_GB   3269    // 7
#define F_CB   3276    // 63
#define F_B3   3340    // 2
#define F_X    3342    // 2*63
#define F_Y    3468    // 2*63
#define F_ADJ  3594    // 2*81
#define F_D    3756    // 2*9
#define F_CTX  3774    // 2*45
#define F_ZP   3864    // 128
#define F_CP   3992    // 128  (end 4120)

// ---- one-time W2 -> bf16 hi/lo pack (padded [64][72], pad zeroed) ----
__global__ void prepack_kernel(const float* __restrict__ W2) {
    int i = blockIdx.x * blockDim.x + threadIdx.x;
    if (i < 64 * LDAB) {
        int n = i / LDAB, k = i % LDAB;
        __nv_bfloat16 hi = __float2bfloat16(0.f);
        __nv_bfloat16 lo = hi;
        if (k < 64) {
            float w = W2[n * 64 + k];
            hi = __float2bfloat16(w);
            lo = __float2bfloat16(w - __bfloat162float(hi));
        }
        reinterpret_cast<__nv_bfloat16*>(g_Bhi4)[i] = hi;
        reinterpret_cast<__nv_bfloat16*>(g_Blo4)[i] = lo;
    }
}

__global__ __launch_bounds__(256, 3)
void car_mma6_kernel(const float* __restrict__ x,      // (B,1,9,7)
                     const int*   __restrict__ adj,    // (B,45)
                     const float* __restrict__ ctx,    // (B,1,9,5)
                     const float* __restrict__ gcnW,   // (7,7)
                     const float* __restrict__ gcnB,   // (7,)
                     const float* __restrict__ ctxW,   // (45,63)
                     const float* __restrict__ ctxB,   // (63,)
                     const float* __restrict__ W1,     // (64,2)
                     const float* __restrict__ b1,     // (64,)
                     const float* __restrict__ b2,     // (64,)
                     const float* __restrict__ W3,     // (2,64)
                     const float* __restrict__ b3,     // (2,)
                     float* __restrict__ out,          // (B,2,9,7)
                     int Bn)
{
    extern __shared__ __align__(16) char sm[];
    __nv_bfloat16* sBhi = (__nv_bfloat16*)(sm + OFF_BHI);
    __nv_bfloat16* sBlo = (__nv_bfloat16*)(sm + OFF_BLO);
    float* sF = (float*)(sm + OFF_F);

    const int tid  = threadIdx.x;
    const int wid  = tid >> 5;
    const int lane = tid & 31;

    // ---- phase 1: bulk copies of prepacked weights ----
    {
        uint4* dh = reinterpret_cast<uint4*>(sBhi);
        uint4* dl = reinterpret_cast<uint4*>(sBlo);
        #pragma unroll
        for (int i = tid; i < BPK_U4; i += 256) { dh[i] = g_Bhi4[i]; dl[i] = g_Blo4[i]; }
    }
    {
        const float4* s4 = reinterpret_cast<const float4*>(ctxW);
        float4* d4 = reinterpret_cast<float4*>(sF + F_CTXW);
        for (int i = tid; i < 708; i += 256) d4[i] = s4[i];
        if (tid < 3) sF[F_CTXW + 2832 + tid] = ctxW[2832 + tid];
    }
    if (tid < 128) { sF[F_W1 + tid] = W1[tid]; sF[F_W3 + tid] = W3[tid]; }
    if (tid < 64)  { sF[F_B1 + tid] = b1[tid]; sF[F_B2 + tid] = b2[tid]; }
    if (tid < 49)  sF[F_GW + tid] = gcnW[tid];
    if (tid < 7)   sF[F_GB + tid] = gcnB[tid];
    if (tid < 63)  sF[F_CB + tid] = ctxB[tid];
    if (tid < 2)   sF[F_B3 + tid] = b3[tid];

    // per-sample staging: 2 samples / CTA
    const int grp   = tid >> 7;      // 0..1
    const int inner = tid & 127;
    const int sG    = blockIdx.x * 2 + grp;
    const bool svalid = (sG < Bn);
    if (inner < 81) sF[F_ADJ + grp * 81 + inner] = 0.f;
    if (inner < 63) sF[F_X + grp * 63 + inner] = svalid ? x[sG * 63 + inner] : 0.f;
    if (inner < 45) sF[F_CTX + grp * 45 + inner] = svalid ? ctx[sG * 45 + inner] : 0.f;
    __syncthreads();

    // ---- phase 2: adjacency fill + y = x @ gcnW ----
    if (svalid && inner < 45) {
        int i = c_iu_i[inner], j = c_iu_j[inner];
        sF[F_ADJ + grp * 81 + i * 9 + j] = (adj[sG * 45 + inner] > 0) ? 1.f : 0.f;
    }
    if (inner < 63) {
        int n = inner / 7, f = inner % 7;
        float acc = 0.f;
        #pragma unroll
        for (int k = 0; k < 7; ++k)
            acc = fmaf(sF[F_X + grp * 63 + n * 7 + k], sF[F_GW + k * 7 + f], acc);
        sF[F_Y + grp * 63 + inner] = acc;
    }
    __syncthreads();

    // ---- phase 3: diag=1, degree norm ----
    if (inner < 9) {
        sF[F_ADJ + grp * 81 + inner * 9 + inner] = 1.f;
        float rs = 0.f;
        #pragma unroll
        for (int m = 0; m < 9; ++m) rs += sF[F_ADJ + grp * 81 + inner * 9 + m];
        sF[F_D + grp * 9 + inner] = rsqrtf(fmaxf(rs, 1.f));
    }
    __syncthreads();

    // ---- phase 4a: cooperative per-row zp/cp (once per row) ----
    {
        const int row = tid & 127;
        const int sl  = row >> 6;
        const int g   = row & 63;
        const bool pv = (g < 63) && (blockIdx.x * 2 + sl < Bn);
        if (tid < 128) {
            float c = 0.f;
            if (pv) {
                float a0 = 0.f, a1 = 0.f, a2 = 0.f, a3 = 0.f;
                const float* cw = sF + F_CTXW + g;
                const float* cx = sF + F_CTX + sl * 45;
                #pragma unroll
                for (int i = 0; i < 44; i += 4) {
                    a0 = fmaf(cx[i],     cw[i * 63],       a0);
                    a1 = fmaf(cx[i + 1], cw[(i + 1) * 63], a1);
                    a2 = fmaf(cx[i + 2], cw[(i + 2) * 63], a2);
                    a3 = fmaf(cx[i + 3], cw[(i + 3) * 63], a3);
                }
                a0 = fmaf(cx[44], cw[44 * 63], a0);
                c = fmaxf(sF[F_CB + g] + ((a0 + a1) + (a2 + a3)), 0.f);
            }
            sF[F_CP + row] = c;
        } else {
            float z = 0.f;
            if (pv) {
                const int n = g / 7, f = g % 7;
                float acc = 0.f;
                #pragma unroll
                for (int m = 0; m < 9; ++m)
                    acc = fmaf(sF[F_ADJ + sl * 81 + n * 9 + m] * sF[F_D + sl * 9 + m],
                               sF[F_Y + sl * 63 + m * 7 + f], acc);
                z = fmaf(acc, sF[F_D + sl * 9 + n], sF[F_GB + f]);
            }
            sF[F_ZP + row] = z;
        }
    }
    __syncthreads();

    // ---- phase 4b: cooperative h1 -> SMEM bf16 hi/lo (each thread: 1 row-half) ----
    {
        const int row  = tid >> 1;          // 0..127
        const int half = (tid & 1) * 32;    // channel base
        const float z = sF[F_ZP + row];
        const float c = sF[F_CP + row];
        uint32_t hibuf[16], lobuf[16];
        #pragma unroll
        for (int j = 0; j < 16; ++j) {
            const int ch = half + 2 * j;
            const float4 w4 = *reinterpret_cast<const float4*>(sF + F_W1 + 2 * ch);
            const float2 bb = *reinterpret_cast<const float2*>(sF + F_B1 + ch);
            float v0 = fmaxf(fmaf(z, w4.x, fmaf(c, w4.y, bb.x)), 0.f);
            float v1 = fmaxf(fmaf(z, w4.z, fmaf(c, w4.w, bb.y)), 0.f);
            split_pack(v0, v1, hibuf[j], lobuf[j]);
        }
        char* rh = sm + OFF_AHI + row * (LDAB * 2) + half * 2;
        char* rl = sm + OFF_ALO + row * (LDAB * 2) + half * 2;
        #pragma unroll
        for (int q = 0; q < 4; ++q) {
            *reinterpret_cast<uint4*>(rh + q * 16) =
                make_uint4(hibuf[4*q], hibuf[4*q+1], hibuf[4*q+2], hibuf[4*q+3]);
            *reinterpret_cast<uint4*>(rl + q * 16) =
                make_uint4(lobuf[4*q], lobuf[4*q+1], lobuf[4*q+2], lobuf[4*q+3]);
        }
    }
    __syncthreads();

    // ---- phase 5: pure ldmatrix + mma k-loop (warp = 16 rows x 64 cols) ----
    float C[8][4];
    #pragma unroll
    for (int n = 0; n < 8; ++n)
        #pragma unroll
        for (int q = 0; q < 4; ++q) C[n][q] = 0.f;

    const uint32_t sub = (uint32_t)(lane >> 3);
    const uint32_t j7  = (uint32_t)(lane & 7);
    const uint32_t aOff = ((sub & 1) * 8 + j7) * (LDAB * 2) + (sub >> 1) * 16;
    const uint32_t aHiBase = smem_u32(sm + OFF_AHI) + (uint32_t)(wid * 16) * (LDAB * 2) + aOff;
    const uint32_t aLoBase = smem_u32(sm + OFF_ALO) + (uint32_t)(wid * 16) * (LDAB * 2) + aOff;
    const uint32_t bOff = ((sub >> 1) * 8 + j7) * (LDAB * 2) + (sub & 1) * 16;
    const uint32_t bHiBase = smem_u32(sBhi) + bOff;
    const uint32_t bLoBase = smem_u32(sBlo) + bOff;

    #pragma unroll
    for (int ks = 0; ks < 4; ++ks) {
        const uint32_t kB = (uint32_t)ks * 32;   // 16 bf16 = 32 bytes
        uint32_t ah[4], al[4];
        ldsm4(ah, aHiBase + kB);
        ldsm4(al, aLoBase + kB);
        #pragma unroll
        for (int nh = 0; nh < 2; ++nh) {
            uint32_t bh[2][4], bl[2][4];
            ldsm4(bh[0], bHiBase + (uint32_t)(nh * 32)      * (LDAB * 2) + kB);
            ldsm4(bh[1], bHiBase + (uint32_t)(nh * 32 + 16) * (LDAB * 2) + kB);
            ldsm4(bl[0], bLoBase + (uint32_t)(nh * 32)      * (LDAB * 2) + kB);
            ldsm4(bl[1], bLoBase + (uint32_t)(nh * 32 + 16) * (LDAB * 2) + kB);
            #pragma unroll
            for (int t = 0; t < 4; ++t) {
                const int nt = nh * 4 + t;
                const uint32_t b0h = bh[t >> 1][(t & 1) * 2];
                const uint32_t b1h = bh[t >> 1][(t & 1) * 2 + 1];
                const uint32_t b0l = bl[t >> 1][(t & 1) * 2];
                const uint32_t b1l = bl[t >> 1][(t & 1) * 2 + 1];
                mma16816(C[nt], ah, b0h, b1h);   // hi*hi
                mma16816(C[nt], ah, b0l, b1l);   // hi*lo
                mma16816(C[nt], al, b0h, b1h);   // lo*hi
            }
        }
    }

    // ---- phase 6: in-register epilogue: relu+b2, W3 dot, quad reduce ----
    const int l4  = lane >> 2;
    const int lm4 = lane & 3;
    const int r0  = wid * 16 + l4;

    float o00 = 0.f, o01 = 0.f, o10 = 0.f, o11 = 0.f;
    #pragma unroll
    for (int nt = 0; nt < 8; ++nt) {
        const int cc = nt * 8 + lm4 * 2;
        const float2 b2v = *reinterpret_cast<const float2*>(sF + F_B2 + cc);
        const float2 w3a = *reinterpret_cast<const float2*>(sF + F_W3 + cc);
        const float2 w3b = *reinterpret_cast<const float2*>(sF + F_W3 + 64 + cc);
        float h0 = fmaxf(C[nt][0] + b2v.x, 0.f);
        float h1 = fmaxf(C[nt][1] + b2v.y, 0.f);
        o00 = fmaf(w3a.x, h0, fmaf(w3a.y, h1, o00));
        o01 = fmaf(w3b.x, h0, fmaf(w3b.y, h1, o01));
        h0 = fmaxf(C[nt][2] + b2v.x, 0.f);
        h1 = fmaxf(C[nt][3] + b2v.y, 0.f);
        o10 = fmaf(w3a.x, h0, fmaf(w3a.y, h1, o10));
        o11 = fmaf(w3b.x, h0, fmaf(w3b.y, h1, o11));
    }
    o00 += __shfl_xor_sync(0xffffffffu, o00, 1);
    o00 += __shfl_xor_sync(0xffffffffu, o00, 2);
    o01 += __shfl_xor_sync(0xffffffffu, o01, 1);
    o01 += __shfl_xor_sync(0xffffffffu, o01, 2);
    o10 += __shfl_xor_sync(0xffffffffu, o10, 1);
    o10 += __shfl_xor_sync(0xffffffffu, o10, 2);
    o11 += __shfl_xor_sync(0xffffffffu, o11, 1);
    o11 += __shfl_xor_sync(0xffffffffu, o11, 2);

    if (lm4 == 0) {
        const float bb30 = sF[F_B3 + 0], bb31 = sF[F_B3 + 1];
        #pragma unroll
        for (int e = 0; e < 2; ++e) {
            const int row = r0 + 8 * e;
            const int sl  = row >> 6;
            const int g   = row & 63;
            const int sO  = blockIdx.x * 2 + sl;
            if (g < 63 && sO < Bn) {
                out[sO * 126 + g]      = ((e == 0) ? o00 : o10) + bb30;
                out[sO * 126 + 63 + g] = ((e == 0) ? o01 : o11) + bb31;
            }
        }
    }
}

extern "C" void kernel_launch(void* const* d_in, const int* in_sizes, int n_in,
                              void* d_out, int out_size) {
    const float* x    = (const float*)d_in[0];
    const int*   adj  = (const int*)  d_in[1];
    const float* ctx  = (const float*)d_in[2];
    const float* gcnW = (const float*)d_in[3];
    const float* gcnB = (const float*)d_in[4];
    const float* ctxW = (const float*)d_in[5];
    const float* ctxB = (const float*)d_in[6];
    const float* W1   = (const float*)d_in[7];
    const float* b1   = (const float*)d_in[8];
    const float* W2   = (const float*)d_in[9];
    const float* b2   = (const float*)d_in[10];
    const float* W3   = (const float*)d_in[11];
    const float* b3   = (const float*)d_in[12];
    float* outp = (float*)d_out;

    cudaFuncSetAttribute(car_mma6_kernel,
                         cudaFuncAttributeMaxDynamicSharedMemorySize, SMEM_BYTES);

    prepack_kernel<<<18, 256>>>(W2);

    int Bn = in_sizes[0] / 63;
    int grid = (Bn + 1) / 2;
    car_mma6_kernel<<<grid, 256, SMEM_BYTES>>>(x, adj, ctx, gcnW, gcnB, ctxW, ctxB,
                                               W1, b1, b2, W3, b3, outp, Bn);
}

// round 11
// speedup vs baseline: 1.2864x; 1.2864x over previous
#include <cuda_runtime.h>
#include <cuda_bf16.h>
#include <cstdint>

// ============================================================
// R7 structure (best: 225.6us) + instruction diet:
//   - cheap bf16 hi/lo split (cvt.rn.bf16x2 + shift/mask reconstruct)
//   - transposed ctxW (prepacked) -> float4 cp dot
//   - vectorized param staging
// CTA = 256 thr, 2 samples (M=128), warp = 16 rows x 64 cols.
// ============================================================

#define LDAB 72   // bf16 row stride for B tiles (144 B)
#define BPK_U4 (64 * LDAB * 2 / 16)   // 576 uint4 per tile
#define CWT_STRIDE 52                 // floats; odd multiple of 4 -> conflict-free LDS.128
#define CWT_F4 ((63 * CWT_STRIDE) / 4)  // 819 float4

__device__ uint4  g_Bhi4[BPK_U4];
__device__ uint4  g_Blo4[BPK_U4];
__device__ float4 g_cwT4[CWT_F4];

__device__ __forceinline__ uint32_t smem_u32(const void* p) {
    uint32_t a;
    asm("{ .reg .u64 t; cvta.to.shared.u64 t, %1; cvt.u32.u64 %0, t; }" : "=r"(a) : "l"(p));
    return a;
}

__device__ __forceinline__ void ldsm4(uint32_t r[4], uint32_t addr) {
    asm volatile("ldmatrix.sync.aligned.m8n8.x4.shared.b16 {%0,%1,%2,%3}, [%4];"
                 : "=r"(r[0]), "=r"(r[1]), "=r"(r[2]), "=r"(r[3]) : "r"(addr));
}

__device__ __forceinline__ void mma16816(float c[4], const uint32_t a[4],
                                          uint32_t b0, uint32_t b1) {
    asm volatile("mma.sync.aligned.m16n8k16.row.col.f32.bf16.bf16.f32 "
                 "{%0,%1,%2,%3}, {%4,%5,%6,%7}, {%8,%9}, {%0,%1,%2,%3};"
                 : "+f"(c[0]), "+f"(c[1]), "+f"(c[2]), "+f"(c[3])
                 : "r"(a[0]), "r"(a[1]), "r"(a[2]), "r"(a[3]), "r"(b0), "r"(b1));
}

// cheap 3-instruction-per-pair-cheaper split: {lo=a, hi=b} bf16x2 + residual pair
__device__ __forceinline__ void split_pack(float a, float b, uint32_t& hi, uint32_t& lo) {
    uint32_t h;
    asm("cvt.rn.bf16x2.f32 %0, %1, %2;" : "=r"(h) : "f"(b), "f"(a));  // hi-half=b, lo-half=a
    float fa = __uint_as_float(h << 16);
    float fb = __uint_as_float(h & 0xffff0000u);
    uint32_t l;
    asm("cvt.rn.bf16x2.f32 %0, %1, %2;" : "=r"(l) : "f"(b - fb), "f"(a - fa));
    hi = h; lo = l;
}

// triu(9) index tables
__constant__ unsigned char c_iu_i[45] = {
    0,0,0,0,0,0,0,0,0, 1,1,1,1,1,1,1,1, 2,2,2,2,2,2,2,
    3,3,3,3,3,3, 4,4,4,4,4, 5,5,5,5, 6,6,6, 7,7, 8};
__constant__ unsigned char c_iu_j[45] = {
    0,1,2,3,4,5,6,7,8, 1,2,3,4,5,6,7,8, 2,3,4,5,6,7,8,
    3,4,5,6,7,8, 4,5,6,7,8, 5,6,7,8, 6,7,8, 7,8, 8};

// float misc region offsets (all float4-critical bases % 4 == 0)
#define F_CW   0       // 3276 (63 x 52)
#define F_W1   3276    // 128
#define F_B1   3404    // 64
#define F_B2   3468    // 64
#define F_W3   3532    // 128
#define F_GW   3660    // 49
#define F_GB   3709    // 7
#define F_CB   3716    // 63
#define F_B3   3779    // 2
#define F_X    3781    // 2*63
#define F_Y    3907    // 2*63
#define F_ADJ  4033    // 2*81
#define F_D    4195    // 2*9
#define F_CTX  4216    // 2*48 (stride 48, zero padded; 16B aligned)
#define F_ZP   4312    // 128
#define F_CP   4440    // 128
#define F_TOTAL 4568

// ---- one-time prepack: W2 -> bf16 hi/lo [64][72]; ctxW -> transposed [63][52] ----
__global__ void prepack_kernel(const float* __restrict__ W2,
                               const float* __restrict__ ctxW) {
    int i = blockIdx.x * blockDim.x + threadIdx.x;
    if (i < 64 * LDAB) {
        int n = i / LDAB, k = i % LDAB;
        __nv_bfloat16 hi = __float2bfloat16(0.f);
        __nv_bfloat16 lo = hi;
        if (k < 64) {
            float w = W2[n * 64 + k];
            hi = __float2bfloat16(w);
            lo = __float2bfloat16(w - __bfloat162float(hi));
        }
        reinterpret_cast<__nv_bfloat16*>(g_Bhi4)[i] = hi;
        reinterpret_cast<__nv_bfloat16*>(g_Blo4)[i] = lo;
    }
    if (i < 63 * CWT_STRIDE) {
        int g = i / CWT_STRIDE, col = i % CWT_STRIDE;
        reinterpret_cast<float*>(g_cwT4)[i] = (col < 45) ? ctxW[col * 63 + g] : 0.f;
    }
}

__global__ __launch_bounds__(256, 3)
void car_mma7_kernel(const float* __restrict__ x,      // (B,1,9,7)
                     const int*   __restrict__ adj,    // (B,45)
                     const float* __restrict__ ctx,    // (B,1,9,5)
                     const float* __restrict__ gcnW,   // (7,7)
                     const float* __restrict__ gcnB,   // (7,)
                     const float* __restrict__ ctxB,   // (63,)
                     const float* __restrict__ W1,     // (64,2)
                     const float* __restrict__ b1,     // (64,)
                     const float* __restrict__ b2,     // (64,)
                     const float* __restrict__ W3,     // (2,64)
                     const float* __restrict__ b3,     // (2,)
                     float* __restrict__ out,          // (B,2,9,7)
                     int Bn)
{
    __shared__ __align__(16) __nv_bfloat16 sBhi[64 * LDAB];
    __shared__ __align__(16) __nv_bfloat16 sBlo[64 * LDAB];
    __shared__ __align__(16) float sF[F_TOTAL];

    const int tid  = threadIdx.x;
    const int wid  = tid >> 5;
    const int lane = tid & 31;

    // ---- phase 1: bulk copies of prepacked weights ----
    {
        uint4* dh = reinterpret_cast<uint4*>(sBhi);
        uint4* dl = reinterpret_cast<uint4*>(sBlo);
        #pragma unroll
        for (int i = tid; i < BPK_U4; i += 256) { dh[i] = g_Bhi4[i]; dl[i] = g_Blo4[i]; }
    }
    {
        float4* d4 = reinterpret_cast<float4*>(sF + F_CW);
        for (int i = tid; i < CWT_F4; i += 256) d4[i] = g_cwT4[i];
    }
    if (tid < 32)                  reinterpret_cast<float4*>(sF + F_W1)[tid]      = reinterpret_cast<const float4*>(W1)[tid];
    else if (tid < 64)             reinterpret_cast<float4*>(sF + F_W3)[tid - 32] = reinterpret_cast<const float4*>(W3)[tid - 32];
    else if (tid < 80)             reinterpret_cast<float4*>(sF + F_B1)[tid - 64] = reinterpret_cast<const float4*>(b1)[tid - 64];
    else if (tid < 96)             reinterpret_cast<float4*>(sF + F_B2)[tid - 80] = reinterpret_cast<const float4*>(b2)[tid - 80];
    else if (tid < 96 + 49)        sF[F_GW + tid - 96] = gcnW[tid - 96];
    else if (tid < 145 + 7)        sF[F_GB + tid - 145] = gcnB[tid - 145];
    else if (tid < 152 + 63)       sF[F_CB + tid - 152] = ctxB[tid - 152];
    else if (tid < 215 + 2)        sF[F_B3 + tid - 215] = b3[tid - 215];

    // per-sample staging: 2 samples / CTA
    const int grp   = tid >> 7;      // 0..1
    const int inner = tid & 127;
    const int sG    = blockIdx.x * 2 + grp;
    const bool svalid = (sG < Bn);
    if (inner < 81) sF[F_ADJ + grp * 81 + inner] = 0.f;
    if (inner < 63) sF[F_X + grp * 63 + inner] = svalid ? x[sG * 63 + inner] : 0.f;
    if (inner < 48) sF[F_CTX + grp * 48 + inner] =
        (inner < 45 && svalid) ? ctx[sG * 45 + inner] : 0.f;
    __syncthreads();

    // ---- phase 2: adjacency fill + y = x @ gcnW ----
    if (svalid && inner < 45) {
        int i = c_iu_i[inner], j = c_iu_j[inner];
        sF[F_ADJ + grp * 81 + i * 9 + j] = (adj[sG * 45 + inner] > 0) ? 1.f : 0.f;
    }
    if (inner < 63) {
        int n = inner / 7, f = inner % 7;
        float acc = 0.f;
        #pragma unroll
        for (int k = 0; k < 7; ++k)
            acc = fmaf(sF[F_X + grp * 63 + n * 7 + k], sF[F_GW + k * 7 + f], acc);
        sF[F_Y + grp * 63 + inner] = acc;
    }
    __syncthreads();

    // ---- phase 3: diag=1, degree norm ----
    if (inner < 9) {
        sF[F_ADJ + grp * 81 + inner * 9 + inner] = 1.f;
        float rs = 0.f;
        #pragma unroll
        for (int m = 0; m < 9; ++m) rs += sF[F_ADJ + grp * 81 + inner * 9 + m];
        sF[F_D + grp * 9 + inner] = rsqrtf(fmaxf(rs, 1.f));
    }
    __syncthreads();

    // ---- phase 4a: cooperative per-row zp/cp (once per row) ----
    {
        const int row = tid & 127;
        const int sl  = row >> 6;
        const int g   = row & 63;
        const bool pv = (g < 63) && (blockIdx.x * 2 + sl < Bn);
        if (tid < 128) {
            float c = 0.f;
            if (pv) {
                const float* cw = sF + F_CW + g * CWT_STRIDE;
                const float* cx = sF + F_CTX + sl * 48;
                float a0 = 0.f, a1 = 0.f, a2 = 0.f, a3 = 0.f;
                #pragma unroll
                for (int i = 0; i < 12; ++i) {
                    const float4 w = *reinterpret_cast<const float4*>(cw + i * 4);
                    const float4 v = *reinterpret_cast<const float4*>(cx + i * 4);
                    a0 = fmaf(v.x, w.x, a0);
                    a1 = fmaf(v.y, w.y, a1);
                    a2 = fmaf(v.z, w.z, a2);
                    a3 = fmaf(v.w, w.w, a3);
                }
                c = fmaxf(sF[F_CB + g] + ((a0 + a1) + (a2 + a3)), 0.f);
            }
            sF[F_CP + row] = c;
        } else {
            float z = 0.f;
            if (pv) {
                const int n = g / 7, f = g % 7;
                float acc = 0.f;
                #pragma unroll
                for (int m = 0; m < 9; ++m)
                    acc = fmaf(sF[F_ADJ + sl * 81 + n * 9 + m] * sF[F_D + sl * 9 + m],
                               sF[F_Y + sl * 63 + m * 7 + f], acc);
                z = fmaf(acc, sF[F_D + sl * 9 + n], sF[F_GB + f]);
            }
            sF[F_ZP + row] = z;
        }
    }
    __syncthreads();

    // ---- phase 4b: lanes fetch their 2 rows' (zp, cp) ----
    const int l4  = lane >> 2;
    const int lm4 = lane & 3;
    const int r0  = wid * 16 + l4;     // rows r0, r0+8 within M=128

    float zp[2], cp[2];
    zp[0] = sF[F_ZP + r0];     zp[1] = sF[F_ZP + r0 + 8];
    cp[0] = sF[F_CP + r0];     cp[1] = sF[F_CP + r0 + 8];

    // ---- phase 5: k-loop, A fragments built in registers, HMMA ----
    float C[8][4];
    #pragma unroll
    for (int n = 0; n < 8; ++n)
        #pragma unroll
        for (int q = 0; q < 4; ++q) C[n][q] = 0.f;

    const uint32_t sub = (uint32_t)(lane >> 3);
    const uint32_t j7  = (uint32_t)(lane & 7);
    const uint32_t bOff = ((sub >> 1) * 8 + j7) * (LDAB * 2) + (sub & 1) * 16;
    const uint32_t bHiBase = smem_u32(sBhi) + bOff;
    const uint32_t bLoBase = smem_u32(sBlo) + bOff;

    #pragma unroll
    for (int ks = 0; ks < 4; ++ks) {
        // A fragments: rows r0, r0+8; channels cb..cb+1 (p=0), cb+8..cb+9 (p=1)
        uint32_t Ahi[4], Alo[4];
        const int cb = lm4 * 2 + ks * 16;
        #pragma unroll
        for (int p = 0; p < 2; ++p) {
            const int c = cb + p * 8;
            const float4 w4 = *reinterpret_cast<const float4*>(sF + F_W1 + 2 * c);
            const float2 bb = *reinterpret_cast<const float2*>(sF + F_B1 + c);
            #pragma unroll
            for (int e = 0; e < 2; ++e) {
                float v0 = fmaxf(fmaf(zp[e], w4.x, fmaf(cp[e], w4.y, bb.x)), 0.f);
                float v1 = fmaxf(fmaf(zp[e], w4.z, fmaf(cp[e], w4.w, bb.y)), 0.f);
                split_pack(v0, v1, Ahi[p * 2 + e], Alo[p * 2 + e]);
            }
        }

        const uint32_t kB = (uint32_t)ks * 32;  // 16 bf16 = 32 bytes
        #pragma unroll
        for (int nh = 0; nh < 2; ++nh) {
            uint32_t bh[2][4], bl[2][4];
            ldsm4(bh[0], bHiBase + (uint32_t)(nh * 32)      * (LDAB * 2) + kB);
            ldsm4(bh[1], bHiBase + (uint32_t)(nh * 32 + 16) * (LDAB * 2) + kB);
            ldsm4(bl[0], bLoBase + (uint32_t)(nh * 32)      * (LDAB * 2) + kB);
            ldsm4(bl[1], bLoBase + (uint32_t)(nh * 32 + 16) * (LDAB * 2) + kB);
            #pragma unroll
            for (int t = 0; t < 4; ++t) {
                const int nt = nh * 4 + t;
                const uint32_t b0h = bh[t >> 1][(t & 1) * 2];
                const uint32_t b1h = bh[t >> 1][(t & 1) * 2 + 1];
                const uint32_t b0l = bl[t >> 1][(t & 1) * 2];
                const uint32_t b1l = bl[t >> 1][(t & 1) * 2 + 1];
                mma16816(C[nt], Ahi, b0h, b1h);   // hi*hi
                mma16816(C[nt], Ahi, b0l, b1l);   // hi*lo
                mma16816(C[nt], Alo, b0h, b1h);   // lo*hi
            }
        }
    }

    // ---- phase 6: in-register epilogue: relu+b2, W3 dot, quad reduce ----
    float o00 = 0.f, o01 = 0.f, o10 = 0.f, o11 = 0.f;
    #pragma unroll
    for (int nt = 0; nt < 8; ++nt) {
        const int cc = nt * 8 + lm4 * 2;
        const float2 b2v = *reinterpret_cast<const float2*>(sF + F_B2 + cc);
        const float2 w3a = *reinterpret_cast<const float2*>(sF + F_W3 + cc);
        const float2 w3b = *reinterpret_cast<const float2*>(sF + F_W3 + 64 + cc);
        float h0 = fmaxf(C[nt][0] + b2v.x, 0.f);
        float h1 = fmaxf(C[nt][1] + b2v.y, 0.f);
        o00 = fmaf(w3a.x, h0, fmaf(w3a.y, h1, o00));
        o01 = fmaf(w3b.x, h0, fmaf(w3b.y, h1, o01));
        h0 = fmaxf(C[nt][2] + b2v.x, 0.f);
        h1 = fmaxf(C[nt][3] + b2v.y, 0.f);
        o10 = fmaf(w3a.x, h0, fmaf(w3a.y, h1, o10));
        o11 = fmaf(w3b.x, h0, fmaf(w3b.y, h1, o11));
    }
    o00 += __shfl_xor_sync(0xffffffffu, o00, 1);
    o00 += __shfl_xor_sync(0xffffffffu, o00, 2);
    o01 += __shfl_xor_sync(0xffffffffu, o01, 1);
    o01 += __shfl_xor_sync(0xffffffffu, o01, 2);
    o10 += __shfl_xor_sync(0xffffffffu, o10, 1);
    o10 += __shfl_xor_sync(0xffffffffu, o10, 2);
    o11 += __shfl_xor_sync(0xffffffffu, o11, 1);
    o11 += __shfl_xor_sync(0xffffffffu, o11, 2);

    if (lm4 == 0) {
        const float bb30 = sF[F_B3 + 0], bb31 = sF[F_B3 + 1];
        #pragma unroll
        for (int e = 0; e < 2; ++e) {
            const int row = r0 + 8 * e;
            const int sl  = row >> 6;
            const int g   = row & 63;
            const int sO  = blockIdx.x * 2 + sl;
            if (g < 63 && sO < Bn) {
                out[sO * 126 + g]      = ((e == 0) ? o00 : o10) + bb30;
                out[sO * 126 + 63 + g] = ((e == 0) ? o01 : o11) + bb31;
            }
        }
    }
}

extern "C" void kernel_launch(void* const* d_in, const int* in_sizes, int n_in,
                              void* d_out, int out_size) {
    const float* x    = (const float*)d_in[0];
    const int*   adj  = (const int*)  d_in[1];
    const float* ctx  = (const float*)d_in[2];
    const float* gcnW = (const float*)d_in[3];
    const float* gcnB = (const float*)d_in[4];
    const float* ctxW = (const float*)d_in[5];
    const float* ctxB = (const float*)d_in[6];
    const float* W1   = (const float*)d_in[7];
    const float* b1   = (const float*)d_in[8];
    const float* W2   = (const float*)d_in[9];
    const float* b2   = (const float*)d_in[10];
    const float* W3   = (const float*)d_in[11];
    const float* b3   = (const float*)d_in[12];
    float* outp = (float*)d_out;

    prepack_kernel<<<18, 256>>>(W2, ctxW);

    int Bn = in_sizes[0] / 63;
    int grid = (Bn + 1) / 2;
    car_mma7_kernel<<<grid, 256>>>(x, adj, ctx, gcnW, gcnB, ctxB,
                                   W1, b1, b2, W3, b3, outp, Bn);
}

// round 12
// speedup vs baseline: 1.4903x; 1.1585x over previous
#include <cuda_runtime.h>
#include <cuda_bf16.h>
#include <cstdint>

// ============================================================
// bf16 3-term split HMMA. CTA = 256 thr, 4 samples (M=256).
// Warp = 32 rows x 64 cols (2 m-tiles) -> B ldmatrix traffic per sample halved.
// W2 hi/lo + transposed ctxW prepacked into device globals.
// ============================================================

#define LDAB 72   // bf16 row stride for B tiles (144 B)
#define BPK_U4 (64 * LDAB * 2 / 16)   // 576 uint4 per tile
#define CWT_STRIDE 52                 // floats; conflict-free LDS.128
#define CWT_F4 ((63 * CWT_STRIDE) / 4)  // 819 float4

__device__ uint4  g_Bhi4[BPK_U4];
__device__ uint4  g_Blo4[BPK_U4];
__device__ float4 g_cwT4[CWT_F4];

__device__ __forceinline__ uint32_t smem_u32(const void* p) {
    uint32_t a;
    asm("{ .reg .u64 t; cvta.to.shared.u64 t, %1; cvt.u32.u64 %0, t; }" : "=r"(a) : "l"(p));
    return a;
}

__device__ __forceinline__ void ldsm4(uint32_t r[4], uint32_t addr) {
    asm volatile("ldmatrix.sync.aligned.m8n8.x4.shared.b16 {%0,%1,%2,%3}, [%4];"
                 : "=r"(r[0]), "=r"(r[1]), "=r"(r[2]), "=r"(r[3]) : "r"(addr));
}

__device__ __forceinline__ void mma16816(float c[4], const uint32_t a[4],
                                          uint32_t b0, uint32_t b1) {
    asm volatile("mma.sync.aligned.m16n8k16.row.col.f32.bf16.bf16.f32 "
                 "{%0,%1,%2,%3}, {%4,%5,%6,%7}, {%8,%9}, {%0,%1,%2,%3};"
                 : "+f"(c[0]), "+f"(c[1]), "+f"(c[2]), "+f"(c[3])
                 : "r"(a[0]), "r"(a[1]), "r"(a[2]), "r"(a[3]), "r"(b0), "r"(b1));
}

__device__ __forceinline__ void split_pack(float a, float b, uint32_t& hi, uint32_t& lo) {
    uint32_t h;
    asm("cvt.rn.bf16x2.f32 %0, %1, %2;" : "=r"(h) : "f"(b), "f"(a));
    float fa = __uint_as_float(h << 16);
    float fb = __uint_as_float(h & 0xffff0000u);
    uint32_t l;
    asm("cvt.rn.bf16x2.f32 %0, %1, %2;" : "=r"(l) : "f"(b - fb), "f"(a - fa));
    hi = h; lo = l;
}

// triu(9) index tables
__constant__ unsigned char c_iu_i[45] = {
    0,0,0,0,0,0,0,0,0, 1,1,1,1,1,1,1,1, 2,2,2,2,2,2,2,
    3,3,3,3,3,3, 4,4,4,4,4, 5,5,5,5, 6,6,6, 7,7, 8};
__constant__ unsigned char c_iu_j[45] = {
    0,1,2,3,4,5,6,7,8, 1,2,3,4,5,6,7,8, 2,3,4,5,6,7,8,
    3,4,5,6,7,8, 4,5,6,7,8, 5,6,7,8, 6,7,8, 7,8, 8};

// float misc region offsets (float4-critical bases % 4 == 0)
#define F_CW   0       // 3276 (63 x 52)
#define F_W1   3276    // 128
#define F_B1   3404    // 64
#define F_B2   3468    // 64
#define F_W3   3532    // 128
#define F_GW   3660    // 49
#define F_GB   3709    // 7
#define F_CB   3716    // 63
#define F_B3   3779    // 2
#define F_X    3784    // 4*63 = 252
#define F_Y    4036    // 252
#define F_ADJ  4288    // 4*81 = 324
#define F_D    4612    // 36
#define F_CTX  4648    // 4*48 = 192 (stride 48, zero padded)
#define F_ZP   4840    // 256
#define F_CP   5096    // 256
#define F_TOTAL 5352

// ---- one-time prepack ----
__global__ void prepack_kernel(const float* __restrict__ W2,
                               const float* __restrict__ ctxW) {
    int i = blockIdx.x * blockDim.x + threadIdx.x;
    if (i < 64 * LDAB) {
        int n = i / LDAB, k = i % LDAB;
        __nv_bfloat16 hi = __float2bfloat16(0.f);
        __nv_bfloat16 lo = hi;
        if (k < 64) {
            float w = W2[n * 64 + k];
            hi = __float2bfloat16(w);
            lo = __float2bfloat16(w - __bfloat162float(hi));
        }
        reinterpret_cast<__nv_bfloat16*>(g_Bhi4)[i] = hi;
        reinterpret_cast<__nv_bfloat16*>(g_Blo4)[i] = lo;
    }
    if (i < 63 * CWT_STRIDE) {
        int g = i / CWT_STRIDE, col = i % CWT_STRIDE;
        reinterpret_cast<float*>(g_cwT4)[i] = (col < 45) ? ctxW[col * 63 + g] : 0.f;
    }
}

__global__ __launch_bounds__(256, 2)
void car_mma8_kernel(const float* __restrict__ x,      // (B,1,9,7)
                     const int*   __restrict__ adj,    // (B,45)
                     const float* __restrict__ ctx,    // (B,1,9,5)
                     const float* __restrict__ gcnW,   // (7,7)
                     const float* __restrict__ gcnB,   // (7,)
                     const float* __restrict__ ctxB,   // (63,)
                     const float* __restrict__ W1,     // (64,2)
                     const float* __restrict__ b1,     // (64,)
                     const float* __restrict__ b2,     // (64,)
                     const float* __restrict__ W3,     // (2,64)
                     const float* __restrict__ b3,     // (2,)
                     float* __restrict__ out,          // (B,2,9,7)
                     int Bn)
{
    __shared__ __align__(16) __nv_bfloat16 sBhi[64 * LDAB];
    __shared__ __align__(16) __nv_bfloat16 sBlo[64 * LDAB];
    __shared__ __align__(16) float sF[F_TOTAL];

    const int tid  = threadIdx.x;
    const int wid  = tid >> 5;
    const int lane = tid & 31;

    // ---- phase 1: bulk copies of prepacked weights ----
    {
        uint4* dh = reinterpret_cast<uint4*>(sBhi);
        uint4* dl = reinterpret_cast<uint4*>(sBlo);
        #pragma unroll
        for (int i = tid; i < BPK_U4; i += 256) { dh[i] = g_Bhi4[i]; dl[i] = g_Blo4[i]; }
    }
    {
        float4* d4 = reinterpret_cast<float4*>(sF + F_CW);
        for (int i = tid; i < CWT_F4; i += 256) d4[i] = g_cwT4[i];
    }
    if (tid < 32)                  reinterpret_cast<float4*>(sF + F_W1)[tid]      = reinterpret_cast<const float4*>(W1)[tid];
    else if (tid < 64)             reinterpret_cast<float4*>(sF + F_W3)[tid - 32] = reinterpret_cast<const float4*>(W3)[tid - 32];
    else if (tid < 80)             reinterpret_cast<float4*>(sF + F_B1)[tid - 64] = reinterpret_cast<const float4*>(b1)[tid - 64];
    else if (tid < 96)             reinterpret_cast<float4*>(sF + F_B2)[tid - 80] = reinterpret_cast<const float4*>(b2)[tid - 80];
    else if (tid < 96 + 49)        sF[F_GW + tid - 96] = gcnW[tid - 96];
    else if (tid < 145 + 7)        sF[F_GB + tid - 145] = gcnB[tid - 145];
    else if (tid < 152 + 63)       sF[F_CB + tid - 152] = ctxB[tid - 152];
    else if (tid < 215 + 2)        sF[F_B3 + tid - 215] = b3[tid - 215];

    // per-sample staging: 4 samples / CTA (grp = tid>>6)
    const int grp = tid >> 6;        // 0..3
    const int g64 = tid & 63;
    const int sG  = blockIdx.x * 4 + grp;
    const bool svalid = (sG < Bn);
    sF[F_ADJ + grp * 81 + g64] = 0.f;
    if (g64 < 17) sF[F_ADJ + grp * 81 + 64 + g64] = 0.f;
    if (g64 < 63) sF[F_X + grp * 63 + g64] = svalid ? x[sG * 63 + g64] : 0.f;
    if (g64 < 48) sF[F_CTX + grp * 48 + g64] =
        (g64 < 45 && svalid) ? ctx[sG * 45 + g64] : 0.f;
    __syncthreads();

    // ---- phase 2: adjacency fill + y = x @ gcnW ----
    if (svalid && g64 < 45) {
        int i = c_iu_i[g64], j = c_iu_j[g64];
        sF[F_ADJ + grp * 81 + i * 9 + j] = (adj[sG * 45 + g64] > 0) ? 1.f : 0.f;
    }
    if (g64 < 63) {
        int n = g64 / 7, f = g64 % 7;
        float acc = 0.f;
        #pragma unroll
        for (int k = 0; k < 7; ++k)
            acc = fmaf(sF[F_X + grp * 63 + n * 7 + k], sF[F_GW + k * 7 + f], acc);
        sF[F_Y + grp * 63 + g64] = acc;
    }
    __syncthreads();

    // ---- phase 3: diag=1, degree norm ----
    if (g64 < 9) {
        sF[F_ADJ + grp * 81 + g64 * 9 + g64] = 1.f;
        float rs = 0.f;
        #pragma unroll
        for (int m = 0; m < 9; ++m) rs += sF[F_ADJ + grp * 81 + g64 * 9 + m];
        sF[F_D + grp * 9 + g64] = rsqrtf(fmaxf(rs, 1.f));
    }
    __syncthreads();

    // ---- phase 4a: per-row zp AND cp (one row per thread, 256 rows) ----
    {
        const int row = tid;
        const int sl  = row >> 6;
        const int g   = row & 63;
        const bool pv = (g < 63) && (blockIdx.x * 4 + sl < Bn);
        float c = 0.f, z = 0.f;
        if (pv) {
            const float* cw = sF + F_CW + g * CWT_STRIDE;
            const float* cx = sF + F_CTX + sl * 48;
            float a0 = 0.f, a1 = 0.f, a2 = 0.f, a3 = 0.f;
            #pragma unroll
            for (int i = 0; i < 12; ++i) {
                const float4 w = *reinterpret_cast<const float4*>(cw + i * 4);
                const float4 v = *reinterpret_cast<const float4*>(cx + i * 4);
                a0 = fmaf(v.x, w.x, a0);
                a1 = fmaf(v.y, w.y, a1);
                a2 = fmaf(v.z, w.z, a2);
                a3 = fmaf(v.w, w.w, a3);
            }
            c = fmaxf(sF[F_CB + g] + ((a0 + a1) + (a2 + a3)), 0.f);

            const int n = g / 7, f = g % 7;
            float acc = 0.f;
            #pragma unroll
            for (int m = 0; m < 9; ++m)
                acc = fmaf(sF[F_ADJ + sl * 81 + n * 9 + m] * sF[F_D + sl * 9 + m],
                           sF[F_Y + sl * 63 + m * 7 + f], acc);
            z = fmaf(acc, sF[F_D + sl * 9 + n], sF[F_GB + f]);
        }
        sF[F_CP + row] = c;
        sF[F_ZP + row] = z;
    }
    __syncthreads();

    // ---- phase 4b: lanes fetch their 4 rows' (zp, cp) ----
    const int l4  = lane >> 2;
    const int lm4 = lane & 3;
    const int r0  = wid * 32 + l4;     // rows r0+8e, e=0..3 (m-tile = e>>1)

    float zp[4], cp[4];
    #pragma unroll
    for (int e = 0; e < 4; ++e) {
        zp[e] = sF[F_ZP + r0 + 8 * e];
        cp[e] = sF[F_CP + r0 + 8 * e];
    }

    // ---- phase 5: k-loop, 2 m-tiles, A in registers, HMMA ----
    float C[2][8][4];
    #pragma unroll
    for (int m = 0; m < 2; ++m)
        #pragma unroll
        for (int n = 0; n < 8; ++n)
            #pragma unroll
            for (int q = 0; q < 4; ++q) C[m][n][q] = 0.f;

    const uint32_t sub = (uint32_t)(lane >> 3);
    const uint32_t j7  = (uint32_t)(lane & 7);
    const uint32_t bOff = ((sub >> 1) * 8 + j7) * (LDAB * 2) + (sub & 1) * 16;
    const uint32_t bHiBase = smem_u32(sBhi) + bOff;
    const uint32_t bLoBase = smem_u32(sBlo) + bOff;

    #pragma unroll
    for (int ks = 0; ks < 4; ++ks) {
        uint32_t Ahi[2][4], Alo[2][4];
        const int cb = lm4 * 2 + ks * 16;
        #pragma unroll
        for (int p = 0; p < 2; ++p) {
            const int c = cb + p * 8;
            const float4 w4 = *reinterpret_cast<const float4*>(sF + F_W1 + 2 * c);
            const float2 bb = *reinterpret_cast<const float2*>(sF + F_B1 + c);
            #pragma unroll
            for (int m = 0; m < 2; ++m) {
                #pragma unroll
                for (int e = 0; e < 2; ++e) {
                    const int r = 2 * m + e;
                    float v0 = fmaxf(fmaf(zp[r], w4.x, fmaf(cp[r], w4.y, bb.x)), 0.f);
                    float v1 = fmaxf(fmaf(zp[r], w4.z, fmaf(cp[r], w4.w, bb.y)), 0.f);
                    split_pack(v0, v1, Ahi[m][p * 2 + e], Alo[m][p * 2 + e]);
                }
            }
        }

        const uint32_t kB = (uint32_t)ks * 32;  // 16 bf16 = 32 bytes
        #pragma unroll
        for (int nh = 0; nh < 2; ++nh) {
            uint32_t bh[2][4], bl[2][4];
            ldsm4(bh[0], bHiBase + (uint32_t)(nh * 32)      * (LDAB * 2) + kB);
            ldsm4(bh[1], bHiBase + (uint32_t)(nh * 32 + 16) * (LDAB * 2) + kB);
            ldsm4(bl[0], bLoBase + (uint32_t)(nh * 32)      * (LDAB * 2) + kB);
            ldsm4(bl[1], bLoBase + (uint32_t)(nh * 32 + 16) * (LDAB * 2) + kB);
            #pragma unroll
            for (int t = 0; t < 4; ++t) {
                const int nt = nh * 4 + t;
                const uint32_t b0h = bh[t >> 1][(t & 1) * 2];
                const uint32_t b1h = bh[t >> 1][(t & 1) * 2 + 1];
                const uint32_t b0l = bl[t >> 1][(t & 1) * 2];
                const uint32_t b1l = bl[t >> 1][(t & 1) * 2 + 1];
                #pragma unroll
                for (int m = 0; m < 2; ++m) {
                    mma16816(C[m][nt], Ahi[m], b0h, b1h);   // hi*hi
                    mma16816(C[m][nt], Ahi[m], b0l, b1l);   // hi*lo
                    mma16816(C[m][nt], Alo[m], b0h, b1h);   // lo*hi
                }
            }
        }
    }

    // ---- phase 6: in-register epilogue per m-tile ----
    float o[2][2][2];   // [m][e][ch]
    #pragma unroll
    for (int m = 0; m < 2; ++m)
        #pragma unroll
        for (int e = 0; e < 2; ++e) { o[m][e][0] = 0.f; o[m][e][1] = 0.f; }

    #pragma unroll
    for (int nt = 0; nt < 8; ++nt) {
        const int cc = nt * 8 + lm4 * 2;
        const float2 b2v = *reinterpret_cast<const float2*>(sF + F_B2 + cc);
        const float2 w3a = *reinterpret_cast<const float2*>(sF + F_W3 + cc);
        const float2 w3b = *reinterpret_cast<const float2*>(sF + F_W3 + 64 + cc);
        #pragma unroll
        for (int m = 0; m < 2; ++m) {
            float h0 = fmaxf(C[m][nt][0] + b2v.x, 0.f);
            float h1 = fmaxf(C[m][nt][1] + b2v.y, 0.f);
            o[m][0][0] = fmaf(w3a.x, h0, fmaf(w3a.y, h1, o[m][0][0]));
            o[m][0][1] = fmaf(w3b.x, h0, fmaf(w3b.y, h1, o[m][0][1]));
            h0 = fmaxf(C[m][nt][2] + b2v.x, 0.f);
            h1 = fmaxf(C[m][nt][3] + b2v.y, 0.f);
            o[m][1][0] = fmaf(w3a.x, h0, fmaf(w3a.y, h1, o[m][1][0]));
            o[m][1][1] = fmaf(w3b.x, h0, fmaf(w3b.y, h1, o[m][1][1]));
        }
    }
    #pragma unroll
    for (int m = 0; m < 2; ++m)
        #pragma unroll
        for (int e = 0; e < 2; ++e)
            #pragma unroll
            for (int ch = 0; ch < 2; ++ch) {
                o[m][e][ch] += __shfl_xor_sync(0xffffffffu, o[m][e][ch], 1);
                o[m][e][ch] += __shfl_xor_sync(0xffffffffu, o[m][e][ch], 2);
            }

    if (lm4 == 0) {
        const float bb30 = sF[F_B3 + 0], bb31 = sF[F_B3 + 1];
        #pragma unroll
        for (int m = 0; m < 2; ++m)
            #pragma unroll
            for (int e = 0; e < 2; ++e) {
                const int row = r0 + m * 16 + e * 8;
                const int sl  = row >> 6;
                const int g   = row & 63;
                const int sO  = blockIdx.x * 4 + sl;
                if (g < 63 && sO < Bn) {
                    out[sO * 126 + g]      = o[m][e][0] + bb30;
                    out[sO * 126 + 63 + g] = o[m][e][1] + bb31;
                }
            }
    }
}

extern "C" void kernel_launch(void* const* d_in, const int* in_sizes, int n_in,
                              void* d_out, int out_size) {
    const float* x    = (const float*)d_in[0];
    const int*   adj  = (const int*)  d_in[1];
    const float* ctx  = (const float*)d_in[2];
    const float* gcnW = (const float*)d_in[3];
    const float* gcnB = (const float*)d_in[4];
    const float* ctxW = (const float*)d_in[5];
    const float* ctxB = (const float*)d_in[6];
    const float* W1   = (const float*)d_in[7];
    const float* b1   = (const float*)d_in[8];
    const float* W2   = (const float*)d_in[9];
    const float* b2   = (const float*)d_in[10];
    const float* W3   = (const float*)d_in[11];
    const float* b3   = (const float*)d_in[12];
    float* outp = (float*)d_out;

    prepack_kernel<<<18, 256>>>(W2, ctxW);

    int Bn = in_sizes[0] / 63;
    int grid = (Bn + 3) / 4;
    car_mma8_kernel<<<grid, 256>>>(x, adj, ctx, gcnW, gcnB, ctxB,
                                   W1, b1, b2, W3, b3, outp, Bn);
}